// round 6
// baseline (speedup 1.0000x reference)
#include <cuda_runtime.h>
#include <math.h>

#define TT 32768
#define BB 64
#define SS 512
#define HH 768
#define CC 50
#define MM 2000
#define TW 1024          /* TT/32 */
#define NK 64            /* split-K chunks for final gemm */
#define KCH (TT/NK)      /* 512 tokens per chunk */
#define CP 52            /* C padded to multiple of 4 */
#define MLMAX 2048       /* max mentions per character (safe bound) */

// ---------------- scratch (static device memory; no allocations) ----------------
__device__ float g_e_nts[TT], g_vn[TT], g_e_mts[TT], g_vm[TT], g_e_uts[TT], g_vc[TT];
__device__ float g_den_m[MM], g_mscore[MM], g_coef[MM];
__device__ unsigned g_mbit[MM * TW];            // 8 MB mention-activity bitmask
__device__ int   g_mlist[CC * MLMAX];
__device__ int   g_mcnt[CC];
__device__ int   g_hasmen[CC];
__device__ float g_q[CC * BB];
__device__ float g_uttp[CC * 8];
__device__ float g_invu[CC];
__device__ int   g_hasutt[CC];
__device__ float g_gsum[(size_t)CC * TT];
__device__ float g_scorep[CC * 8 * 3];
__device__ float g_WT[(size_t)TT * CP];
__device__ float g_partial[(size_t)NK * CC * HH];

// ---------------- helpers ----------------
__device__ __forceinline__ float warpSum(float v) {
#pragma unroll
    for (int o = 16; o; o >>= 1) v += __shfl_down_sync(0xffffffffu, v, o);
    return v;
}
__device__ __forceinline__ float warpSumAll(float v) {
#pragma unroll
    for (int o = 16; o; o >>= 1) v += __shfl_xor_sync(0xffffffffu, v, o);
    return v;
}
__device__ __forceinline__ float warpMaxAll(float v) {
#pragma unroll
    for (int o = 16; o; o >>= 1) v = fmaxf(v, __shfl_xor_sync(0xffffffffu, v, o));
    return v;
}
__device__ __forceinline__ float blockReduceSum(float v, float* sb) {
    __syncthreads();
    int lane = threadIdx.x & 31, w = threadIdx.x >> 5;
    v = warpSum(v);
    if (lane == 0) sb[w] = v;
    __syncthreads();
    float r = 0.f;
    if (w == 0) {
        int nw = blockDim.x >> 5;
        r = (lane < nw) ? sb[lane] : 0.f;
        r = warpSum(r);
    }
    return r;
}
__device__ __forceinline__ unsigned long long fma2(unsigned long long a,
                                                   unsigned long long b,
                                                   unsigned long long c) {
    unsigned long long d;
    asm("fma.rn.f32x2 %0, %1, %2, %3;" : "=l"(d) : "l"(a), "l"(b), "l"(c));
    return d;
}
__device__ __forceinline__ float dot4(float4 a, float4 b) {
    return a.x * b.x + a.y * b.y + a.z * b.z + a.w * b.w;
}

// ---------------- K1: per-token scalar projections; 4 tokens per warp ----------------
__global__ void __launch_bounds__(256) k_token(const float* __restrict__ se,
                        const float* __restrict__ wnt, const float* __restrict__ bnt,
                        const float* __restrict__ wn,  const float* __restrict__ bn,
                        const float* __restrict__ wmt, const float* __restrict__ bmt,
                        const float* __restrict__ wm,  const float* __restrict__ bm,
                        const float* __restrict__ wu,  const float* __restrict__ bu,
                        const float* __restrict__ wc,  const float* __restrict__ bc) {
    int warp = (blockIdx.x * blockDim.x + threadIdx.x) >> 5;
    int lane = threadIdx.x & 31;
    int t0 = warp * 4;                       // 4 consecutive tokens per warp
    if (t0 >= TT) return;
    const float4* r0 = reinterpret_cast<const float4*>(se) + (size_t)t0 * (HH / 4);
    const float4* W0 = reinterpret_cast<const float4*>(wnt);
    const float4* W1 = reinterpret_cast<const float4*>(wn);
    const float4* W2 = reinterpret_cast<const float4*>(wmt);
    const float4* W3 = reinterpret_cast<const float4*>(wm);
    const float4* W4 = reinterpret_cast<const float4*>(wu);
    const float4* W5 = reinterpret_cast<const float4*>(wc);
    float acc[4][6];
#pragma unroll
    for (int tk = 0; tk < 4; tk++)
#pragma unroll
        for (int p = 0; p < 6; p++) acc[tk][p] = 0.f;
#pragma unroll
    for (int i = 0; i < (HH / 4) / 32; i++) {
        int j = i * 32 + lane;
        float4 w0 = W0[j], w1 = W1[j], w2 = W2[j], w3 = W3[j], w4 = W4[j], w5 = W5[j];
#pragma unroll
        for (int tk = 0; tk < 4; tk++) {
            float4 v = r0[(size_t)tk * (HH / 4) + j];
            acc[tk][0] += dot4(v, w0);
            acc[tk][1] += dot4(v, w1);
            acc[tk][2] += dot4(v, w2);
            acc[tk][3] += dot4(v, w3);
            acc[tk][4] += dot4(v, w4);
            acc[tk][5] += dot4(v, w5);
        }
    }
#pragma unroll
    for (int tk = 0; tk < 4; tk++)
#pragma unroll
        for (int p = 0; p < 6; p++) acc[tk][p] = warpSum(acc[tk][p]);
    if (lane == 0) {
        float vbnt = *bnt, vbn = *bn, vbmt = *bmt, vbm = *bm, vbu = *bu, vbc = *bc;
#pragma unroll
        for (int tk = 0; tk < 4; tk++) {
            int t = t0 + tk;
            g_e_nts[t] = expf(acc[tk][0] + vbnt);
            g_vn[t]    = acc[tk][1] + vbn;
            g_e_mts[t] = expf(acc[tk][2] + vbmt);
            g_vm[t]    = acc[tk][3] + vbm;
            g_e_uts[t] = expf(acc[tk][4] + vbu);
            g_vc[t]    = acc[tk][5] + vbc;
        }
    }
}

// ---------------- K2: utterance denominator partials, grid (CC, 8) ----------------
__global__ void k_utt(const float* __restrict__ umask) {
    int c = blockIdx.x, ch = blockIdx.y;
    const float4* row = reinterpret_cast<const float4*>(umask + (size_t)c * TT) + ch * 1024;
    const float* eu = g_e_uts + ch * 4096;
    float du = 0.f;
#pragma unroll
    for (int k = 0; k < 4; k++) {
        int i = k * 256 + threadIdx.x;
        float4 v = row[i];
        int t = i * 4;
        if (v.x == 0.f) du += eu[t + 0];
        if (v.y == 0.f) du += eu[t + 1];
        if (v.z == 0.f) du += eu[t + 2];
        if (v.w == 0.f) du += eu[t + 3];
    }
    __shared__ float sb[8];
    float d = blockReduceSum(du, sb);
    if (threadIdx.x == 0) g_uttp[c * 8 + ch] = d;
}

// ---------------- K3: fused name rep ----------------
__global__ void k_names(const float* __restrict__ nmask, const float* __restrict__ bname) {
    int c = blockIdx.x;
    __shared__ float smask[SS];
    __shared__ float sden[BB], snsc[BB];
    for (int i = threadIdx.x; i < SS; i += 256) smask[i] = nmask[c * SS + i];
    __syncthreads();
    int w = threadIdx.x >> 5, lane = threadIdx.x & 31;
    float bn_v = *bname;
    for (int b = w; b < BB; b += 8) {
        float den = 0.f, num = 0.f;
        for (int s = lane; s < SS; s += 32) {
            if (smask[s] == 0.f) {
                float e = g_e_nts[b * SS + s];
                den += e;
                num = fmaf(e, g_vn[b * SS + s], num);
            }
        }
        den = warpSumAll(den); num = warpSumAll(num);
        if (lane == 0) { sden[b] = den; snsc[b] = num / den + bn_v; }
    }
    __syncthreads();
    if (threadIdx.x < BB) {
        float v = snsc[threadIdx.x];
        float mx = -INFINITY;
#pragma unroll
        for (int i = 0; i < BB; i++) mx = fmaxf(mx, snsc[i]);
        float sum = 0.f;
#pragma unroll
        for (int i = 0; i < BB; i++) sum += expf(snsc[i] - mx);
        g_q[c * BB + threadIdx.x] = (expf(v - mx) / sum) / sden[threadIdx.x];
    }
}

// ---------------- K4: mention pass (262MB read; bitmask build) — PROFILED slot ----------------
__global__ void k_m1(const float* __restrict__ mmask, const float* __restrict__ bmen) {
    int m = blockIdx.x;
    const float4* row = reinterpret_cast<const float4*>(mmask + (size_t)m * TT);
    float den = 0.f, num = 0.f;
#pragma unroll 1
    for (int wi = threadIdx.x; wi < TW; wi += 256) {
        int t0 = wi * 32;
        unsigned bits = 0;
#pragma unroll
        for (int q8 = 0; q8 < 8; q8++) {
            float4 v = row[wi * 8 + q8];
            if (v.x == 0.f) bits |= 1u << (q8 * 4 + 0);
            if (v.y == 0.f) bits |= 1u << (q8 * 4 + 1);
            if (v.z == 0.f) bits |= 1u << (q8 * 4 + 2);
            if (v.w == 0.f) bits |= 1u << (q8 * 4 + 3);
        }
        g_mbit[(size_t)m * TW + wi] = bits;
        if (bits) {
            unsigned rem = bits;
            do {
                int b = __ffs(rem) - 1; rem &= rem - 1;
                int t = t0 + b;
                float e = g_e_mts[t];
                den += e;
                num = fmaf(e, g_vm[t], num);
            } while (rem);
        }
    }
    __shared__ float sb[8];
    float bmen_v = *bmen;
    float d = blockReduceSum(den, sb);
    float n = blockReduceSum(num, sb);
    if (threadIdx.x == 0) {
        g_den_m[m]  = d;
        g_mscore[m] = n / d + bmen_v;
    }
}

// ---------------- K5: mention lists + segment softmax (warp0) + utt reduce (warp1) ----------------
__global__ void k_seg2(const int* __restrict__ seg) {
    int c = blockIdx.x;
    if (threadIdx.x < 32) {
        int lane = threadIdx.x;
        int cnt = 0;
        float mx = -INFINITY;
        for (int base = 0; base < MM; base += 32) {
            int m = base + lane;
            bool match = (m < MM) && (seg[m] == c);
            unsigned bal = __ballot_sync(0xffffffffu, match);
            if (match) {
                int pos = cnt + __popc(bal & ((1u << lane) - 1u));
                g_mlist[c * MLMAX + pos] = m;
                mx = fmaxf(mx, g_mscore[m]);
            }
            cnt += __popc(bal);
        }
        mx = warpMaxAll(mx);
        float sum = 0.f;
        for (int i = lane; i < cnt; i += 32)
            sum += expf(g_mscore[g_mlist[c * MLMAX + i]] - mx);
        sum = warpSumAll(sum);
        for (int i = lane; i < cnt; i += 32) {
            int m = g_mlist[c * MLMAX + i];
            g_coef[m] = expf(g_mscore[m] - mx) / (sum * g_den_m[m]);
        }
        if (lane == 0) { g_mcnt[c] = cnt; g_hasmen[c] = (cnt > 0) ? 1 : 0; }
    } else {
        int l = threadIdx.x - 32;
        float p = (l < 8) ? g_uttp[c * 8 + l] : 0.f;
        p = warpSumAll(p);
        if (l == 0) {
            g_hasutt[c] = (p > 0.f) ? 1 : 0;
            g_invu[c]   = (p > 0.f) ? 1.f / p : 0.f;
        }
    }
}

// ---------------- K6: gsum[c,t] ----------------
__global__ void k_gsum() {
    __shared__ float st[128 * 33];
    int c = blockIdx.x;
    int wbase = blockIdx.y * 128 + threadIdx.x;
    int cnt = g_mcnt[c];
    const int* list = g_mlist + c * MLMAX;
    float s[32];
#pragma unroll
    for (int b = 0; b < 32; b++) s[b] = 0.f;
    for (int i = 0; i < cnt; i++) {
        int m = list[i];
        unsigned w = g_mbit[(size_t)m * TW + wbase];
        if (w) {
            float cf = g_coef[m];
#pragma unroll
            for (int b = 0; b < 32; b++)
                if ((w >> b) & 1u) s[b] += cf;
        }
    }
#pragma unroll
    for (int b = 0; b < 32; b++) st[threadIdx.x * 33 + b] = s[b];
    __syncthreads();
    float* dst = g_gsum + (size_t)c * TT + (size_t)blockIdx.y * 4096;
    for (int j = threadIdx.x; j < 4096; j += 128)
        dst[j] = st[(j >> 5) * 33 + (j & 31)];
}

// ---------------- K7: combine scores ----------------
__global__ void k_scores(const float* __restrict__ nmask, const float* __restrict__ umask) {
    int c = blockIdx.x, ch = blockIdx.y;
    int t0 = ch * (TT / 8);
    float invu = g_invu[c];
    float s0 = 0.f, s1 = 0.f, s2 = 0.f;
    for (int t = t0 + threadIdx.x; t < t0 + TT / 8; t += 256) {
        float vcv = g_vc[t];
        int b = t >> 9, s = t & (SS - 1);
        float wN = (nmask[c * SS + s] == 0.f) ? g_q[c * BB + b] * g_e_nts[t] : 0.f;
        float wM = g_gsum[(size_t)c * TT + t] * g_e_mts[t];
        float wU = (umask[(size_t)c * TT + t] == 0.f) ? g_e_uts[t] * invu : 0.f;
        s0 = fmaf(wN, vcv, s0);
        s1 = fmaf(wM, vcv, s1);
        s2 = fmaf(wU, vcv, s2);
    }
    __shared__ float sb[8];
    float r0 = blockReduceSum(s0, sb);
    float r1 = blockReduceSum(s1, sb);
    float r2 = blockReduceSum(s2, sb);
    if (threadIdx.x == 0) {
        g_scorep[(c * 8 + ch) * 3 + 0] = r0;
        g_scorep[(c * 8 + ch) * 3 + 1] = r1;
        g_scorep[(c * 8 + ch) * 3 + 2] = r2;
    }
}

// ---------------- K8: final combined token weights [T, Cpad] ----------------
__global__ void k_wt(const float* __restrict__ nmask, const float* __restrict__ umask,
                     const float* __restrict__ bcomb) {
    __shared__ float sw[128 * CP];
    __shared__ float sattn[CC * 3];
    int t0 = blockIdx.x * 128;
    int t = t0 + threadIdx.x;
    if (threadIdx.x < CC) {
        int c = threadIdx.x;
        float s0 = 0.f, s1 = 0.f, s2 = 0.f;
#pragma unroll
        for (int k = 0; k < 8; k++) {
            s0 += g_scorep[(c * 8 + k) * 3 + 0];
            s1 += g_scorep[(c * 8 + k) * 3 + 1];
            s2 += g_scorep[(c * 8 + k) * 3 + 2];
        }
        float bc = *bcomb;
        s0 += bc;
        s1 = g_hasmen[c] ? s1 + bc : -INFINITY;
        s2 = g_hasutt[c] ? s2 + bc : -INFINITY;
        float mx = fmaxf(s0, fmaxf(s1, s2));
        float e0 = expf(s0 - mx), e1 = expf(s1 - mx), e2 = expf(s2 - mx);
        float inv = 1.f / (e0 + e1 + e2);
        sattn[c * 3 + 0] = e0 * inv;
        sattn[c * 3 + 1] = e1 * inv;
        sattn[c * 3 + 2] = e2 * inv;
    }
    __syncthreads();
    float en = g_e_nts[t], em = g_e_mts[t], eu = g_e_uts[t];
    int b = t >> 9, s = t & (SS - 1);
#pragma unroll 1
    for (int c = 0; c < CC; c++) {
        float a0 = sattn[c * 3 + 0], a1 = sattn[c * 3 + 1], a2 = sattn[c * 3 + 2];
        float wN = (nmask[c * SS + s] == 0.f) ? g_q[c * BB + b] * en : 0.f;
        float wM = g_gsum[(size_t)c * TT + t] * em;
        float wU = (umask[(size_t)c * TT + t] == 0.f) ? eu * g_invu[c] : 0.f;
        sw[threadIdx.x * CP + c] = a0 * wN + a1 * wM + a2 * wU;
    }
    sw[threadIdx.x * CP + 50] = 0.f;
    sw[threadIdx.x * CP + 51] = 0.f;
    __syncthreads();
    float* dst = g_WT + (size_t)t0 * CP;
    for (int i = threadIdx.x; i < 128 * CP; i += 128) dst[i] = sw[i];
}

// ---------------- K9: out = W[C,T] @ se[T,H], split-K with f32x2 FMAs ----------------
__global__ void __launch_bounds__(128) k_gemm(const float* __restrict__ se) {
    __shared__ __align__(16) float sw[64 * CP];
    int kc = blockIdx.x, ht = blockIdx.y;
    int h = ht * 128 + threadIdx.x;
    int t0 = kc * KCH;
    unsigned long long acc[25];
#pragma unroll
    for (int i = 0; i < 25; i++) acc[i] = 0ull;
    for (int tt = 0; tt < KCH; tt += 64) {
        __syncthreads();
        const float* src = g_WT + (size_t)(t0 + tt) * CP;
        for (int i = threadIdx.x; i < 64 * CP; i += 128) sw[i] = src[i];
        __syncthreads();
#pragma unroll 4
        for (int i = 0; i < 64; i++) {
            float sev = se[(size_t)(t0 + tt + i) * HH + h];
            unsigned long long sev2;
            asm("mov.b64 %0, {%1, %1};" : "=l"(sev2) : "f"(sev));
            const ulonglong2* wr = reinterpret_cast<const ulonglong2*>(&sw[i * CP]);
#pragma unroll
            for (int p = 0; p < 12; p++) {
                ulonglong2 w2 = wr[p];
                acc[2 * p]     = fma2(w2.x, sev2, acc[2 * p]);
                acc[2 * p + 1] = fma2(w2.y, sev2, acc[2 * p + 1]);
            }
            unsigned long long wlast =
                reinterpret_cast<const unsigned long long*>(&sw[i * CP])[24];
            acc[24] = fma2(wlast, sev2, acc[24]);
        }
    }
#pragma unroll
    for (int p = 0; p < 25; p++) {
        float2 v = *reinterpret_cast<float2*>(&acc[p]);
        g_partial[((size_t)kc * CC + 2 * p) * HH + h]     = v.x;
        g_partial[((size_t)kc * CC + 2 * p + 1) * HH + h] = v.y;
    }
}

// ---------------- K10: deterministic split-K reduction ----------------
__global__ void k_reduce(float* __restrict__ out) {
    int idx = blockIdx.x * 256 + threadIdx.x;
    if (idx >= CC * HH) return;
    float s0 = 0.f, s1 = 0.f, s2 = 0.f, s3 = 0.f;
#pragma unroll 4
    for (int k = 0; k < NK; k += 4) {
        s0 += g_partial[(size_t)(k + 0) * CC * HH + idx];
        s1 += g_partial[(size_t)(k + 1) * CC * HH + idx];
        s2 += g_partial[(size_t)(k + 2) * CC * HH + idx];
        s3 += g_partial[(size_t)(k + 3) * CC * HH + idx];
    }
    out[idx] = (s0 + s1) + (s2 + s3);
}

// ---------------- launch ----------------
extern "C" void kernel_launch(void* const* d_in, const int* in_sizes, int n_in,
                              void* d_out, int out_size) {
    const float* se    = (const float*)d_in[0];
    const float* nmask = (const float*)d_in[1];
    const float* umask = (const float*)d_in[2];
    const float* mmask = (const float*)d_in[3];
    const int*   seg   = (const int*)d_in[4];
    const float* wnt = (const float*)d_in[5];  const float* bnt = (const float*)d_in[6];
    const float* wn  = (const float*)d_in[7];  const float* bn  = (const float*)d_in[8];
    const float* wmt = (const float*)d_in[9];  const float* bmt = (const float*)d_in[10];
    const float* wm  = (const float*)d_in[11]; const float* bm  = (const float*)d_in[12];
    const float* wu  = (const float*)d_in[13]; const float* bu  = (const float*)d_in[14];
    const float* wc  = (const float*)d_in[15]; const float* bc  = (const float*)d_in[16];
    float* out = (float*)d_out;

    // launch #4 is k_m1 (the 262MB-read kernel) for the ncu capture slot
    k_token<<<TT / 32, 256>>>(se, wnt, bnt, wn, bn, wmt, bmt, wm, bm, wu, bu, wc, bc);
    k_utt<<<dim3(CC, 8), 256>>>(umask);
    k_names<<<CC, 256>>>(nmask, bn);
    k_m1<<<MM, 256>>>(mmask, bm);
    k_seg2<<<CC, 64>>>(seg);
    k_gsum<<<dim3(CC, 8), 128>>>();
    k_scores<<<dim3(CC, 8), 256>>>(nmask, umask);
    k_wt<<<TT / 128, 128>>>(nmask, umask, bc);
    k_gemm<<<dim3(NK, HH / 128), 128>>>(se);
    k_reduce<<<(CC * HH + 255) / 256, 256>>>(out);
}

// round 7
// speedup vs baseline: 1.2873x; 1.2873x over previous
#include <cuda_runtime.h>
#include <math.h>

#define TT 32768
#define BB 64
#define SS 512
#define HH 768
#define CC 50
#define MM 2000
#define TW 1024          /* TT/32 */
#define NK 128           /* split-K chunks for final gemm */
#define KCH (TT/NK)      /* 256 tokens per chunk */
#define CP 52            /* C padded to multiple of 4 */
#define MLMAX 2048       /* max mentions per character (safe bound) */

// ---------------- scratch (static device memory; no allocations) ----------------
__device__ float g_e_nts[TT], g_vn[TT], g_e_mts[TT], g_vm[TT], g_e_uts[TT], g_vc[TT];
__device__ float g_den_m[MM], g_mscore[MM], g_coef[MM];
__device__ unsigned g_mbit[MM * TW];            // 8 MB mention-activity bitmask
__device__ int   g_mlist[CC * MLMAX];
__device__ int   g_mcnt[CC];
__device__ int   g_hasmen[CC];
__device__ float g_q[CC * BB];
__device__ float g_uttp[CC * 8];
__device__ float g_invu[CC];
__device__ int   g_hasutt[CC];
__device__ float g_gsum[(size_t)CC * TT];
__device__ float g_scorep[CC * 8 * 3];
__device__ float g_WT[(size_t)TT * CP];
__device__ float g_partial[(size_t)NK * CC * HH];

// ---------------- helpers ----------------
__device__ __forceinline__ float warpSum(float v) {
#pragma unroll
    for (int o = 16; o; o >>= 1) v += __shfl_down_sync(0xffffffffu, v, o);
    return v;
}
__device__ __forceinline__ float warpSumAll(float v) {
#pragma unroll
    for (int o = 16; o; o >>= 1) v += __shfl_xor_sync(0xffffffffu, v, o);
    return v;
}
__device__ __forceinline__ float warpMaxAll(float v) {
#pragma unroll
    for (int o = 16; o; o >>= 1) v = fmaxf(v, __shfl_xor_sync(0xffffffffu, v, o));
    return v;
}
__device__ __forceinline__ float blockReduceSum(float v, float* sb) {
    __syncthreads();
    int lane = threadIdx.x & 31, w = threadIdx.x >> 5;
    v = warpSum(v);
    if (lane == 0) sb[w] = v;
    __syncthreads();
    float r = 0.f;
    if (w == 0) {
        int nw = blockDim.x >> 5;
        r = (lane < nw) ? sb[lane] : 0.f;
        r = warpSum(r);
    }
    return r;
}
__device__ __forceinline__ unsigned long long fma2(unsigned long long a,
                                                   unsigned long long b,
                                                   unsigned long long c) {
    unsigned long long d;
    asm("fma.rn.f32x2 %0, %1, %2, %3;" : "=l"(d) : "l"(a), "l"(b), "l"(c));
    return d;
}

// ---------------- K1: per-token scalar projections (R2 form: 1 token/warp) ----------------
__global__ void k_token(const float* __restrict__ se,
                        const float* __restrict__ wnt, const float* __restrict__ bnt,
                        const float* __restrict__ wn,  const float* __restrict__ bn,
                        const float* __restrict__ wmt, const float* __restrict__ bmt,
                        const float* __restrict__ wm,  const float* __restrict__ bm,
                        const float* __restrict__ wu,  const float* __restrict__ bu,
                        const float* __restrict__ wc,  const float* __restrict__ bc) {
    int gw = (blockIdx.x * blockDim.x + threadIdx.x) >> 5;
    int lane = threadIdx.x & 31;
    if (gw >= TT) return;
    const float4* row = reinterpret_cast<const float4*>(se) + (size_t)gw * (HH / 4);
    const float4* W0 = reinterpret_cast<const float4*>(wnt);
    const float4* W1 = reinterpret_cast<const float4*>(wn);
    const float4* W2 = reinterpret_cast<const float4*>(wmt);
    const float4* W3 = reinterpret_cast<const float4*>(wm);
    const float4* W4 = reinterpret_cast<const float4*>(wu);
    const float4* W5 = reinterpret_cast<const float4*>(wc);
    float a0 = 0.f, a1 = 0.f, a2 = 0.f, a3 = 0.f, a4 = 0.f, a5 = 0.f;
#pragma unroll
    for (int i = 0; i < (HH / 4) / 32; i++) {
        int j = i * 32 + lane;
        float4 v = row[j];
        float4 w;
        w = W0[j]; a0 += v.x * w.x + v.y * w.y + v.z * w.z + v.w * w.w;
        w = W1[j]; a1 += v.x * w.x + v.y * w.y + v.z * w.z + v.w * w.w;
        w = W2[j]; a2 += v.x * w.x + v.y * w.y + v.z * w.z + v.w * w.w;
        w = W3[j]; a3 += v.x * w.x + v.y * w.y + v.z * w.z + v.w * w.w;
        w = W4[j]; a4 += v.x * w.x + v.y * w.y + v.z * w.z + v.w * w.w;
        w = W5[j]; a5 += v.x * w.x + v.y * w.y + v.z * w.z + v.w * w.w;
    }
    a0 = warpSum(a0); a1 = warpSum(a1); a2 = warpSum(a2);
    a3 = warpSum(a3); a4 = warpSum(a4); a5 = warpSum(a5);
    if (lane == 0) {
        g_e_nts[gw] = expf(a0 + *bnt);
        g_vn[gw]    = a1 + *bn;
        g_e_mts[gw] = expf(a2 + *bmt);
        g_vm[gw]    = a3 + *bm;
        g_e_uts[gw] = expf(a4 + *bu);
        g_vc[gw]    = a5 + *bc;
    }
}

// ---------------- K2: utterance denominator partials, grid (CC, 8) ----------------
__global__ void k_utt(const float* __restrict__ umask) {
    int c = blockIdx.x, ch = blockIdx.y;
    const float4* row = reinterpret_cast<const float4*>(umask + (size_t)c * TT) + ch * 1024;
    const float* eu = g_e_uts + ch * 4096;
    float du = 0.f;
#pragma unroll
    for (int k = 0; k < 4; k++) {
        int i = k * 256 + threadIdx.x;
        float4 v = row[i];
        int t = i * 4;
        if (v.x == 0.f) du += eu[t + 0];
        if (v.y == 0.f) du += eu[t + 1];
        if (v.z == 0.f) du += eu[t + 2];
        if (v.w == 0.f) du += eu[t + 3];
    }
    __shared__ float sb[8];
    float d = blockReduceSum(du, sb);
    if (threadIdx.x == 0) g_uttp[c * 8 + ch] = d;
}

// ---------------- K3: fused name rep ----------------
__global__ void k_names(const float* __restrict__ nmask, const float* __restrict__ bname) {
    int c = blockIdx.x;
    __shared__ float smask[SS];
    __shared__ float sden[BB], snsc[BB];
    for (int i = threadIdx.x; i < SS; i += 256) smask[i] = nmask[c * SS + i];
    __syncthreads();
    int w = threadIdx.x >> 5, lane = threadIdx.x & 31;
    float bn_v = *bname;
    for (int b = w; b < BB; b += 8) {
        float den = 0.f, num = 0.f;
        for (int s = lane; s < SS; s += 32) {
            if (smask[s] == 0.f) {
                float e = g_e_nts[b * SS + s];
                den += e;
                num = fmaf(e, g_vn[b * SS + s], num);
            }
        }
        den = warpSumAll(den); num = warpSumAll(num);
        if (lane == 0) { sden[b] = den; snsc[b] = num / den + bn_v; }
    }
    __syncthreads();
    if (threadIdx.x < BB) {
        float v = snsc[threadIdx.x];
        float mx = -INFINITY;
#pragma unroll
        for (int i = 0; i < BB; i++) mx = fmaxf(mx, snsc[i]);
        float sum = 0.f;
#pragma unroll
        for (int i = 0; i < BB; i++) sum += expf(snsc[i] - mx);
        g_q[c * BB + threadIdx.x] = (expf(v - mx) / sum) / sden[threadIdx.x];
    }
}

// ---------------- K4a: mention mask stream -> bitmask (coalesced + ballot) ----------------
// grid (MM, 2), 256 threads. Warp w handles 2048 consecutive tokens (64 words).
__global__ void __launch_bounds__(256) k_m1a(const float* __restrict__ mmask) {
    int m = blockIdx.x;
    int wid = threadIdx.x >> 5, lane = threadIdx.x & 31;
    int base_t = blockIdx.y * 16384 + wid * 2048;
    const float* row = mmask + (size_t)m * TT;
    unsigned* dst = g_mbit + (size_t)m * TW + (base_t >> 5);
#pragma unroll 1
    for (int j = 0; j < 64; j += 8) {
        unsigned w[8];
#pragma unroll
        for (int k = 0; k < 8; k++) {
            float v = row[base_t + (j + k) * 32 + lane];       // coalesced 128B per warp instr
            w[k] = __ballot_sync(0xffffffffu, v == 0.f);
        }
        if (lane == 0) {
            *reinterpret_cast<uint4*>(dst + j)     = make_uint4(w[0], w[1], w[2], w[3]);
            *reinterpret_cast<uint4*>(dst + j + 4) = make_uint4(w[4], w[5], w[6], w[7]);
        }
    }
}

// ---------------- K4b: mention den/num from bitmask (8MB coalesced + sparse gather) ----------------
__global__ void k_m1b(const float* __restrict__ bmen) {
    int m = blockIdx.x;
    const unsigned* bits = g_mbit + (size_t)m * TW;
    float den = 0.f, num = 0.f;
#pragma unroll
    for (int k = 0; k < 4; k++) {
        int wi = k * 256 + threadIdx.x;                        // coalesced 4B stride
        unsigned b = bits[wi];
        if (b) {
            int t0 = wi * 32;
            do {
                int bb = __ffs(b) - 1; b &= b - 1;
                float e = g_e_mts[t0 + bb];
                den += e;
                num = fmaf(e, g_vm[t0 + bb], num);
            } while (b);
        }
    }
    __shared__ float sb[8];
    float bmen_v = *bmen;
    float d = blockReduceSum(den, sb);
    float n = blockReduceSum(num, sb);
    if (threadIdx.x == 0) {
        g_den_m[m]  = d;
        g_mscore[m] = n / d + bmen_v;
    }
}

// ---------------- K5: mention lists + segment softmax (warp0) + utt reduce (warp1) ----------------
__global__ void k_seg2(const int* __restrict__ seg) {
    int c = blockIdx.x;
    if (threadIdx.x < 32) {
        int lane = threadIdx.x;
        int cnt = 0;
        float mx = -INFINITY;
        for (int base = 0; base < MM; base += 32) {
            int m = base + lane;
            bool match = (m < MM) && (seg[m] == c);
            unsigned bal = __ballot_sync(0xffffffffu, match);
            if (match) {
                int pos = cnt + __popc(bal & ((1u << lane) - 1u));
                g_mlist[c * MLMAX + pos] = m;
                mx = fmaxf(mx, g_mscore[m]);
            }
            cnt += __popc(bal);
        }
        mx = warpMaxAll(mx);
        float sum = 0.f;
        for (int i = lane; i < cnt; i += 32)
            sum += expf(g_mscore[g_mlist[c * MLMAX + i]] - mx);
        sum = warpSumAll(sum);
        for (int i = lane; i < cnt; i += 32) {
            int m = g_mlist[c * MLMAX + i];
            g_coef[m] = expf(g_mscore[m] - mx) / (sum * g_den_m[m]);
        }
        if (lane == 0) { g_mcnt[c] = cnt; g_hasmen[c] = (cnt > 0) ? 1 : 0; }
    } else {
        int l = threadIdx.x - 32;
        float p = (l < 8) ? g_uttp[c * 8 + l] : 0.f;
        p = warpSumAll(p);
        if (l == 0) {
            g_hasutt[c] = (p > 0.f) ? 1 : 0;
            g_invu[c]   = (p > 0.f) ? 1.f / p : 0.f;
        }
    }
}

// ---------------- K6: gsum[c,t] ----------------
__global__ void k_gsum() {
    __shared__ float st[128 * 33];
    int c = blockIdx.x;
    int wbase = blockIdx.y * 128 + threadIdx.x;
    int cnt = g_mcnt[c];
    const int* list = g_mlist + c * MLMAX;
    float s[32];
#pragma unroll
    for (int b = 0; b < 32; b++) s[b] = 0.f;
    for (int i = 0; i < cnt; i++) {
        int m = list[i];
        unsigned w = g_mbit[(size_t)m * TW + wbase];
        if (w) {
            float cf = g_coef[m];
#pragma unroll
            for (int b = 0; b < 32; b++)
                if ((w >> b) & 1u) s[b] += cf;
        }
    }
#pragma unroll
    for (int b = 0; b < 32; b++) st[threadIdx.x * 33 + b] = s[b];
    __syncthreads();
    float* dst = g_gsum + (size_t)c * TT + (size_t)blockIdx.y * 4096;
    for (int j = threadIdx.x; j < 4096; j += 128)
        dst[j] = st[(j >> 5) * 33 + (j & 31)];
}

// ---------------- K7: combine scores ----------------
__global__ void k_scores(const float* __restrict__ nmask, const float* __restrict__ umask) {
    int c = blockIdx.x, ch = blockIdx.y;
    int t0 = ch * (TT / 8);
    float invu = g_invu[c];
    float s0 = 0.f, s1 = 0.f, s2 = 0.f;
    for (int t = t0 + threadIdx.x; t < t0 + TT / 8; t += 256) {
        float vcv = g_vc[t];
        int b = t >> 9, s = t & (SS - 1);
        float wN = (nmask[c * SS + s] == 0.f) ? g_q[c * BB + b] * g_e_nts[t] : 0.f;
        float wM = g_gsum[(size_t)c * TT + t] * g_e_mts[t];
        float wU = (umask[(size_t)c * TT + t] == 0.f) ? g_e_uts[t] * invu : 0.f;
        s0 = fmaf(wN, vcv, s0);
        s1 = fmaf(wM, vcv, s1);
        s2 = fmaf(wU, vcv, s2);
    }
    __shared__ float sb[8];
    float r0 = blockReduceSum(s0, sb);
    float r1 = blockReduceSum(s1, sb);
    float r2 = blockReduceSum(s2, sb);
    if (threadIdx.x == 0) {
        g_scorep[(c * 8 + ch) * 3 + 0] = r0;
        g_scorep[(c * 8 + ch) * 3 + 1] = r1;
        g_scorep[(c * 8 + ch) * 3 + 2] = r2;
    }
}

// ---------------- K8: final combined token weights [T, Cpad] ----------------
__global__ void k_wt(const float* __restrict__ nmask, const float* __restrict__ umask,
                     const float* __restrict__ bcomb) {
    __shared__ float sw[128 * CP];
    __shared__ float sattn[CC * 3];
    int t0 = blockIdx.x * 128;
    int t = t0 + threadIdx.x;
    if (threadIdx.x < CC) {
        int c = threadIdx.x;
        float s0 = 0.f, s1 = 0.f, s2 = 0.f;
#pragma unroll
        for (int k = 0; k < 8; k++) {
            s0 += g_scorep[(c * 8 + k) * 3 + 0];
            s1 += g_scorep[(c * 8 + k) * 3 + 1];
            s2 += g_scorep[(c * 8 + k) * 3 + 2];
        }
        float bc = *bcomb;
        s0 += bc;
        s1 = g_hasmen[c] ? s1 + bc : -INFINITY;
        s2 = g_hasutt[c] ? s2 + bc : -INFINITY;
        float mx = fmaxf(s0, fmaxf(s1, s2));
        float e0 = expf(s0 - mx), e1 = expf(s1 - mx), e2 = expf(s2 - mx);
        float inv = 1.f / (e0 + e1 + e2);
        sattn[c * 3 + 0] = e0 * inv;
        sattn[c * 3 + 1] = e1 * inv;
        sattn[c * 3 + 2] = e2 * inv;
    }
    __syncthreads();
    float en = g_e_nts[t], em = g_e_mts[t], eu = g_e_uts[t];
    int b = t >> 9, s = t & (SS - 1);
#pragma unroll 1
    for (int c = 0; c < CC; c++) {
        float a0 = sattn[c * 3 + 0], a1 = sattn[c * 3 + 1], a2 = sattn[c * 3 + 2];
        float wN = (nmask[c * SS + s] == 0.f) ? g_q[c * BB + b] * en : 0.f;
        float wM = g_gsum[(size_t)c * TT + t] * em;
        float wU = (umask[(size_t)c * TT + t] == 0.f) ? eu * g_invu[c] : 0.f;
        sw[threadIdx.x * CP + c] = a0 * wN + a1 * wM + a2 * wU;
    }
    sw[threadIdx.x * CP + 50] = 0.f;
    sw[threadIdx.x * CP + 51] = 0.f;
    __syncthreads();
    float* dst = g_WT + (size_t)t0 * CP;
    for (int i = threadIdx.x; i < 128 * CP; i += 128) dst[i] = sw[i];
}

// ---------------- K9: out = W[C,T] @ se[T,H], split-K with f32x2 FMAs ----------------
__global__ void __launch_bounds__(128) k_gemm(const float* __restrict__ se) {
    __shared__ __align__(16) float sw[64 * CP];
    int kc = blockIdx.x, ht = blockIdx.y;
    int h = ht * 128 + threadIdx.x;
    int t0 = kc * KCH;
    unsigned long long acc[25];
#pragma unroll
    for (int i = 0; i < 25; i++) acc[i] = 0ull;
    for (int tt = 0; tt < KCH; tt += 64) {
        __syncthreads();
        const float* src = g_WT + (size_t)(t0 + tt) * CP;
        for (int i = threadIdx.x; i < 64 * CP; i += 128) sw[i] = src[i];
        __syncthreads();
#pragma unroll 4
        for (int i = 0; i < 64; i++) {
            float sev = se[(size_t)(t0 + tt + i) * HH + h];
            unsigned long long sev2;
            asm("mov.b64 %0, {%1, %1};" : "=l"(sev2) : "f"(sev));
            const ulonglong2* wr = reinterpret_cast<const ulonglong2*>(&sw[i * CP]);
#pragma unroll
            for (int p = 0; p < 12; p++) {
                ulonglong2 w2 = wr[p];
                acc[2 * p]     = fma2(w2.x, sev2, acc[2 * p]);
                acc[2 * p + 1] = fma2(w2.y, sev2, acc[2 * p + 1]);
            }
            unsigned long long wlast =
                reinterpret_cast<const unsigned long long*>(&sw[i * CP])[24];
            acc[24] = fma2(wlast, sev2, acc[24]);
        }
    }
#pragma unroll
    for (int p = 0; p < 25; p++) {
        float2 v = *reinterpret_cast<float2*>(&acc[p]);
        g_partial[((size_t)kc * CC + 2 * p) * HH + h]     = v.x;
        g_partial[((size_t)kc * CC + 2 * p + 1) * HH + h] = v.y;
    }
}

// ---------------- K10: deterministic split-K reduction ----------------
__global__ void k_reduce(float* __restrict__ out) {
    int idx = blockIdx.x * 256 + threadIdx.x;
    if (idx >= CC * HH) return;
    float s0 = 0.f, s1 = 0.f, s2 = 0.f, s3 = 0.f;
#pragma unroll 4
    for (int k = 0; k < NK; k += 4) {
        s0 += g_partial[(size_t)(k + 0) * CC * HH + idx];
        s1 += g_partial[(size_t)(k + 1) * CC * HH + idx];
        s2 += g_partial[(size_t)(k + 2) * CC * HH + idx];
        s3 += g_partial[(size_t)(k + 3) * CC * HH + idx];
    }
    out[idx] = (s0 + s1) + (s2 + s3);
}

// ---------------- launch ----------------
extern "C" void kernel_launch(void* const* d_in, const int* in_sizes, int n_in,
                              void* d_out, int out_size) {
    const float* se    = (const float*)d_in[0];
    const float* nmask = (const float*)d_in[1];
    const float* umask = (const float*)d_in[2];
    const float* mmask = (const float*)d_in[3];
    const int*   seg   = (const int*)d_in[4];
    const float* wnt = (const float*)d_in[5];  const float* bnt = (const float*)d_in[6];
    const float* wn  = (const float*)d_in[7];  const float* bn  = (const float*)d_in[8];
    const float* wmt = (const float*)d_in[9];  const float* bmt = (const float*)d_in[10];
    const float* wm  = (const float*)d_in[11]; const float* bm  = (const float*)d_in[12];
    const float* wu  = (const float*)d_in[13]; const float* bu  = (const float*)d_in[14];
    const float* wc  = (const float*)d_in[15]; const float* bc  = (const float*)d_in[16];
    float* out = (float*)d_out;

    // launch #4 is k_m1a (the 262MB stream kernel) for the ncu capture slot
    k_token<<<TT / 8, 256>>>(se, wnt, bnt, wn, bn, wmt, bmt, wm, bm, wu, bu, wc, bc);
    k_utt<<<dim3(CC, 8), 256>>>(umask);
    k_names<<<CC, 256>>>(nmask, bn);
    k_m1a<<<dim3(MM, 2), 256>>>(mmask);
    k_m1b<<<MM, 256>>>(bm);
    k_seg2<<<CC, 64>>>(seg);
    k_gsum<<<dim3(CC, 8), 128>>>();
    k_scores<<<dim3(CC, 8), 256>>>(nmask, umask);
    k_wt<<<TT / 128, 128>>>(nmask, umask, bc);
    k_gemm<<<dim3(NK, HH / 128), 128>>>(se);
    k_reduce<<<(CC * HH + 255) / 256, 256>>>(out);
}